// round 15
// baseline (speedup 1.0000x reference)
#include <cuda_runtime.h>
#include <cuda_fp16.h>
#include <math.h>
#include <float.h>

#define N_NODES 100000
#define N_EDGES 1600000
#define ETOT    (N_EDGES + N_NODES)
#define IN_DIM  256
#define HID     128
#define OUTD    64
#define NEG_SLOPE 0.2f
#define SCAN_NB ((N_NODES + 255) / 256)   // 391
#define N_PROBE 16384
#define FULLM 0xffffffffu

// ---------------- scratch (static device globals; no allocation) ----------------
static __device__ __align__(128) float g_o1[(size_t)N_NODES * HID];   // streamed
static __device__ __align__(128) float g_o2[(size_t)N_NODES * OUTD];  // streamed
static __device__ float g_ssrc[N_NODES];
static __device__ float g_sdst[N_NODES];
static __device__ int   g_cnt[N_NODES];
static __device__ int   g_cur[N_NODES];
static __device__ int   g_off[N_NODES + 1];
static __device__ int   g_bsum[512];
static __device__ int   g_col[ETOT];

// ---------------- CSR build (verbatim, verified) ----------------
__global__ void k_zeroA() {
    int i = blockIdx.x * blockDim.x + threadIdx.x;
    if (i < N_NODES) g_cnt[i] = 0;
}
__global__ void k_zeroB() {
    int i = blockIdx.x * blockDim.x + threadIdx.x;
    if (i < N_NODES) g_cur[i] = 0;
}

__global__ void k_count(const int* __restrict__ ei) {
    int t = blockIdx.x * blockDim.x + threadIdx.x;
    if (t >= ETOT) return;
    int dst = (t < N_EDGES) ? ei[N_EDGES + t] : (t - N_EDGES);
    atomicAdd(&g_cnt[dst], 1);
}

__global__ void k_scan1() {
    __shared__ int s[256];
    int t = threadIdx.x, idx = blockIdx.x * 256 + t;
    int v = (idx < N_NODES) ? g_cnt[idx] : 0;
    s[t] = v; __syncthreads();
    #pragma unroll
    for (int o = 1; o < 256; o <<= 1) {
        int u = (t >= o) ? s[t - o] : 0;
        __syncthreads();
        s[t] += u;
        __syncthreads();
    }
    if (idx < N_NODES) g_off[idx] = s[t] - v;
    if (t == 255) g_bsum[blockIdx.x] = s[t];
}

__global__ void k_scan2(int nb) {
    __shared__ int s[512];
    int t = threadIdx.x;
    int v = (t < nb) ? g_bsum[t] : 0;
    s[t] = v; __syncthreads();
    #pragma unroll
    for (int o = 1; o < 512; o <<= 1) {
        int u = (t >= o) ? s[t - o] : 0;
        __syncthreads();
        s[t] += u;
        __syncthreads();
    }
    g_bsum[t] = s[t] - v;
}

__global__ void k_scan3() {
    int t = threadIdx.x, idx = blockIdx.x * 256 + t;
    if (idx < N_NODES) g_off[idx] += g_bsum[blockIdx.x];
    if (idx == 0) g_off[N_NODES] = ETOT;
}

__global__ void k_fill(const int* __restrict__ ei) {
    int t = blockIdx.x * blockDim.x + threadIdx.x;
    if (t >= ETOT) return;
    int src, dst;
    if (t < N_EDGES) { src = ei[t]; dst = ei[N_EDGES + t]; }
    else             { src = dst = t - N_EDGES; }
    int pos = g_off[dst] + atomicAdd(&g_cur[dst], 1);
    g_col[pos] = src;
}

// ---------------- tensor-core GEMM1 (verbatim, verified) ----------------
__global__ void __launch_bounds__(256) k_gemm1_mma(
        const float* __restrict__ A, const float* __restrict__ W,
        __half* __restrict__ Hout,
        const float* __restrict__ asrc, const float* __restrict__ adst,
        float* __restrict__ ssrc, float* __restrict__ sdst, int M) {
    constexpr int BM = 64;
    __shared__ __half As[BM][24];
    __shared__ __half Bs[128][20];
    __shared__ __half Hs[BM][136];

    const int tid = threadIdx.x;
    const int w   = tid >> 5;
    const int lane = tid & 31;
    const int g = lane >> 2;
    const int t = lane & 3;
    const int wm = (w & 1) * 32;
    const int wn = (w >> 1) * 32;
    const int m0 = blockIdx.x * BM;

    float c[2][4][4];
    #pragma unroll
    for (int mf = 0; mf < 2; mf++)
        #pragma unroll
        for (int nf = 0; nf < 4; nf++)
            #pragma unroll
            for (int q = 0; q < 4; q++) c[mf][nf][q] = 0.f;

    const int arow = tid >> 2;
    const int ac4  = (tid & 3) * 4;

    for (int k0 = 0; k0 < IN_DIM; k0 += 16) {
        {
            float4 v = make_float4(0.f, 0.f, 0.f, 0.f);
            int gr = m0 + arow;
            if (gr < M) v = *(const float4*)(A + (size_t)gr * IN_DIM + k0 + ac4);
            *(__half2*)&As[arow][ac4]     = __floats2half2_rn(v.x, v.y);
            *(__half2*)&As[arow][ac4 + 2] = __floats2half2_rn(v.z, v.w);
        }
        #pragma unroll
        for (int i = tid; i < 16 * 32; i += 256) {
            int kk = i >> 5;
            int n4 = (i & 31) * 4;
            float4 wv = *(const float4*)(W + (size_t)(k0 + kk) * HID + n4);
            Bs[n4 + 0][kk] = __float2half_rn(wv.x);
            Bs[n4 + 1][kk] = __float2half_rn(wv.y);
            Bs[n4 + 2][kk] = __float2half_rn(wv.z);
            Bs[n4 + 3][kk] = __float2half_rn(wv.w);
        }
        __syncthreads();

        unsigned a[2][4];
        #pragma unroll
        for (int mf = 0; mf < 2; mf++) {
            int r = wm + mf * 16;
            a[mf][0] = *(const unsigned*)&As[r + g][2 * t];
            a[mf][1] = *(const unsigned*)&As[r + 8 + g][2 * t];
            a[mf][2] = *(const unsigned*)&As[r + g][2 * t + 8];
            a[mf][3] = *(const unsigned*)&As[r + 8 + g][2 * t + 8];
        }
        #pragma unroll
        for (int nf = 0; nf < 4; nf++) {
            int n = wn + nf * 8;
            unsigned b0 = *(const unsigned*)&Bs[n + g][2 * t];
            unsigned b1 = *(const unsigned*)&Bs[n + g][2 * t + 8];
            #pragma unroll
            for (int mf = 0; mf < 2; mf++) {
                asm volatile(
                    "mma.sync.aligned.m16n8k16.row.col.f32.f16.f16.f32 "
                    "{%0,%1,%2,%3}, {%4,%5,%6,%7}, {%8,%9}, {%0,%1,%2,%3};"
                    : "+f"(c[mf][nf][0]), "+f"(c[mf][nf][1]),
                      "+f"(c[mf][nf][2]), "+f"(c[mf][nf][3])
                    : "r"(a[mf][0]), "r"(a[mf][1]), "r"(a[mf][2]), "r"(a[mf][3]),
                      "r"(b0), "r"(b1));
            }
        }
        __syncthreads();
    }

    #pragma unroll
    for (int mf = 0; mf < 2; mf++) {
        #pragma unroll
        for (int nf = 0; nf < 4; nf++) {
            int r0 = wm + mf * 16 + g;
            int cc = wn + nf * 8 + 2 * t;
            *(__half2*)&Hs[r0][cc]     = __floats2half2_rn(c[mf][nf][0], c[mf][nf][1]);
            *(__half2*)&Hs[r0 + 8][cc] = __floats2half2_rn(c[mf][nf][2], c[mf][nf][3]);
        }
    }
    __syncthreads();

    #pragma unroll
    for (int i = tid; i < 64 * 16; i += 256) {
        int row = i >> 4, seg = i & 15;
        if (m0 + row < M) {
            uint4 v = *(const uint4*)&Hs[row][seg * 8];
            *(uint4*)(Hout + (size_t)(m0 + row) * HID + seg * 8) = v;
        }
    }

    float4 a1v = *(const float4*)(asrc + lane * 4);
    float4 a2v = *(const float4*)(adst + lane * 4);
    #pragma unroll
    for (int r = 0; r < 8; r++) {
        int row = w * 8 + r;
        uint2 hv = *(const uint2*)&Hs[row][lane * 4];
        const __half* hp = reinterpret_cast<const __half*>(&hv);
        float f0 = __half2float(hp[0]), f1 = __half2float(hp[1]);
        float f2 = __half2float(hp[2]), f3 = __half2float(hp[3]);
        float d1 = f0 * a1v.x + f1 * a1v.y + f2 * a1v.z + f3 * a1v.w;
        float d2 = f0 * a2v.x + f1 * a2v.y + f2 * a2v.z + f3 * a2v.w;
        #pragma unroll
        for (int o = 16; o; o >>= 1) {
            d1 += __shfl_xor_sync(FULLM, d1, o);
            d2 += __shfl_xor_sync(FULLM, d2, o);
        }
        if (lane == 0 && m0 + row < M) {
            ssrc[m0 + row] = d1;
            sdst[m0 + row] = d2;
        }
    }
}

// ---------------- tensor-core GEMM2 (verbatim, verified) ----------------
__global__ void __launch_bounds__(256) k_gemm2_mma(
        const float* __restrict__ A, const float* __restrict__ W,
        float* __restrict__ Hout,
        const float* __restrict__ asrc, const float* __restrict__ adst,
        float* __restrict__ ssrc, float* __restrict__ sdst, int M) {
    constexpr int BM = 64;
    __shared__ __half As[BM][24];
    __shared__ __half Bs[64][20];
    __shared__ float  Hs[BM][68];

    const int tid = threadIdx.x;
    const int w   = tid >> 5;
    const int lane = tid & 31;
    const int g = lane >> 2;
    const int t = lane & 3;
    const int wm = (w & 3) * 16;
    const int wn = (w >> 2) * 32;
    const int m0 = blockIdx.x * BM;

    float c[4][4];
    #pragma unroll
    for (int nf = 0; nf < 4; nf++)
        #pragma unroll
        for (int q = 0; q < 4; q++) c[nf][q] = 0.f;

    const int arow = tid >> 2;
    const int ac4  = (tid & 3) * 4;

    for (int k0 = 0; k0 < HID; k0 += 16) {
        {
            float4 v = make_float4(0.f, 0.f, 0.f, 0.f);
            int gr = m0 + arow;
            if (gr < M) v = *(const float4*)(A + (size_t)gr * HID + k0 + ac4);
            *(__half2*)&As[arow][ac4]     = __floats2half2_rn(v.x, v.y);
            *(__half2*)&As[arow][ac4 + 2] = __floats2half2_rn(v.z, v.w);
        }
        {
            int kk = tid >> 4;
            int n4 = (tid & 15) * 4;
            float4 wv = *(const float4*)(W + (size_t)(k0 + kk) * OUTD + n4);
            Bs[n4 + 0][kk] = __float2half_rn(wv.x);
            Bs[n4 + 1][kk] = __float2half_rn(wv.y);
            Bs[n4 + 2][kk] = __float2half_rn(wv.z);
            Bs[n4 + 3][kk] = __float2half_rn(wv.w);
        }
        __syncthreads();

        unsigned a[4];
        a[0] = *(const unsigned*)&As[wm + g][2 * t];
        a[1] = *(const unsigned*)&As[wm + 8 + g][2 * t];
        a[2] = *(const unsigned*)&As[wm + g][2 * t + 8];
        a[3] = *(const unsigned*)&As[wm + 8 + g][2 * t + 8];
        #pragma unroll
        for (int nf = 0; nf < 4; nf++) {
            int n = wn + nf * 8;
            unsigned b0 = *(const unsigned*)&Bs[n + g][2 * t];
            unsigned b1 = *(const unsigned*)&Bs[n + g][2 * t + 8];
            asm volatile(
                "mma.sync.aligned.m16n8k16.row.col.f32.f16.f16.f32 "
                "{%0,%1,%2,%3}, {%4,%5,%6,%7}, {%8,%9}, {%0,%1,%2,%3};"
                : "+f"(c[nf][0]), "+f"(c[nf][1]), "+f"(c[nf][2]), "+f"(c[nf][3])
                : "r"(a[0]), "r"(a[1]), "r"(a[2]), "r"(a[3]),
                  "r"(b0), "r"(b1));
        }
        __syncthreads();
    }

    #pragma unroll
    for (int nf = 0; nf < 4; nf++) {
        int cc = wn + nf * 8 + 2 * t;
        Hs[wm + g][cc]     = c[nf][0];
        Hs[wm + g][cc + 1] = c[nf][1];
        Hs[wm + 8 + g][cc]     = c[nf][2];
        Hs[wm + 8 + g][cc + 1] = c[nf][3];
    }
    __syncthreads();

    #pragma unroll
    for (int i = tid; i < 64 * 16; i += 256) {
        int row = i >> 4, seg = (i & 15) * 4;
        if (m0 + row < M) {
            float4 v = *(const float4*)&Hs[row][seg];
            *(float4*)(Hout + (size_t)(m0 + row) * OUTD + seg) = v;
        }
    }

    float2 a1v = *(const float2*)(asrc + lane * 2);
    float2 a2v = *(const float2*)(adst + lane * 2);
    #pragma unroll
    for (int r = 0; r < 8; r++) {
        int row = w * 8 + r;
        float2 hv = *(const float2*)&Hs[row][lane * 2];
        float d1 = hv.x * a1v.x + hv.y * a1v.y;
        float d2 = hv.x * a2v.x + hv.y * a2v.y;
        #pragma unroll
        for (int o = 16; o; o >>= 1) {
            d1 += __shfl_xor_sync(FULLM, d1, o);
            d2 += __shfl_xor_sync(FULLM, d2, o);
        }
        if (lane == 0 && m0 + row < M) {
            ssrc[m0 + row] = d1;
            sdst[m0 + row] = d2;
        }
    }
}

// ---------------- agg v4 core (layer 1): single-pass, PLAIN exp, no serial chain ----
// |e| <= ~15 for this data (glorot weights), far from fp32 exp overflow (88),
// so max-subtraction is unnecessary; softmax ratios are identical.
struct RealColsV { const int* __restrict__ col;
    __device__ __forceinline__ int operator()(int j) const { return col[j]; } };
struct HashColsV { unsigned seed;
    __device__ __forceinline__ int operator()(int j) const {
        unsigned v = seed + (unsigned)j * 40503u;
        v ^= v >> 13; v *= 2246822519u; v ^= v >> 16;
        return (int)(v % N_NODES);
    } };

template<class ColFn>
__device__ __forceinline__ void aggH_core(int node, ColFn colf, int beg, int end,
        const __half* __restrict__ h, float sd, const float4 a1v,
        const float* __restrict__ bias, float* __restrict__ out, int lane) {
    float s = 0.f;
    float acc0 = 0.f, acc1 = 0.f, acc2 = 0.f, acc3 = 0.f;

    for (int c0 = beg; c0 < end; c0 += 32) {
        int n = min(32, end - c0);
        int cs = (lane < n) ? colf(c0 + lane) : 0;

        int k = 0;
        for (; k + 4 <= n; k += 4) {
            int s0 = __shfl_sync(FULLM, cs, k);
            int s1 = __shfl_sync(FULLM, cs, k + 1);
            int s2 = __shfl_sync(FULLM, cs, k + 2);
            int s3 = __shfl_sync(FULLM, cs, k + 3);
            uint2 r0 = *(const uint2*)(h + (size_t)s0 * HID + lane * 4);
            uint2 r1 = *(const uint2*)(h + (size_t)s1 * HID + lane * 4);
            uint2 r2 = *(const uint2*)(h + (size_t)s2 * HID + lane * 4);
            uint2 r3 = *(const uint2*)(h + (size_t)s3 * HID + lane * 4);
            const __half* p0 = reinterpret_cast<const __half*>(&r0);
            const __half* p1 = reinterpret_cast<const __half*>(&r1);
            const __half* p2 = reinterpret_cast<const __half*>(&r2);
            const __half* p3 = reinterpret_cast<const __half*>(&r3);
            float f0a = __half2float(p0[0]), f0b = __half2float(p0[1]),
                  f0c = __half2float(p0[2]), f0d = __half2float(p0[3]);
            float f1a = __half2float(p1[0]), f1b = __half2float(p1[1]),
                  f1c = __half2float(p1[2]), f1d = __half2float(p1[3]);
            float f2a = __half2float(p2[0]), f2b = __half2float(p2[1]),
                  f2c = __half2float(p2[2]), f2d = __half2float(p2[3]);
            float f3a = __half2float(p3[0]), f3b = __half2float(p3[1]),
                  f3c = __half2float(p3[2]), f3d = __half2float(p3[3]);
            float d0 = f0a * a1v.x + f0b * a1v.y + f0c * a1v.z + f0d * a1v.w;
            float d1 = f1a * a1v.x + f1b * a1v.y + f1c * a1v.z + f1d * a1v.w;
            float d2 = f2a * a1v.x + f2b * a1v.y + f2c * a1v.z + f2d * a1v.w;
            float d3 = f3a * a1v.x + f3b * a1v.y + f3c * a1v.z + f3d * a1v.w;
            #pragma unroll
            for (int o = 16; o; o >>= 1) {
                d0 += __shfl_xor_sync(FULLM, d0, o);
                d1 += __shfl_xor_sync(FULLM, d1, o);
                d2 += __shfl_xor_sync(FULLM, d2, o);
                d3 += __shfl_xor_sync(FULLM, d3, o);
            }
            float e0 = d0 + sd; e0 = (e0 > 0.f) ? e0 : NEG_SLOPE * e0;
            float e1 = d1 + sd; e1 = (e1 > 0.f) ? e1 : NEG_SLOPE * e1;
            float e2 = d2 + sd; e2 = (e2 > 0.f) ? e2 : NEG_SLOPE * e2;
            float e3 = d3 + sd; e3 = (e3 > 0.f) ? e3 : NEG_SLOPE * e3;
            float w0 = __expf(e0), w1 = __expf(e1), w2 = __expf(e2), w3 = __expf(e3);
            s += (w0 + w1) + (w2 + w3);
            acc0 = fmaf(w0, f0a, acc0); acc1 = fmaf(w0, f0b, acc1);
            acc2 = fmaf(w0, f0c, acc2); acc3 = fmaf(w0, f0d, acc3);
            acc0 = fmaf(w1, f1a, acc0); acc1 = fmaf(w1, f1b, acc1);
            acc2 = fmaf(w1, f1c, acc2); acc3 = fmaf(w1, f1d, acc3);
            acc0 = fmaf(w2, f2a, acc0); acc1 = fmaf(w2, f2b, acc1);
            acc2 = fmaf(w2, f2c, acc2); acc3 = fmaf(w2, f2d, acc3);
            acc0 = fmaf(w3, f3a, acc0); acc1 = fmaf(w3, f3b, acc1);
            acc2 = fmaf(w3, f3c, acc2); acc3 = fmaf(w3, f3d, acc3);
        }
        for (; k < n; k++) {
            int s0 = __shfl_sync(FULLM, cs, k);
            uint2 r0 = *(const uint2*)(h + (size_t)s0 * HID + lane * 4);
            const __half* p0 = reinterpret_cast<const __half*>(&r0);
            float f0a = __half2float(p0[0]), f0b = __half2float(p0[1]),
                  f0c = __half2float(p0[2]), f0d = __half2float(p0[3]);
            float d0 = f0a * a1v.x + f0b * a1v.y + f0c * a1v.z + f0d * a1v.w;
            #pragma unroll
            for (int o = 16; o; o >>= 1) d0 += __shfl_xor_sync(FULLM, d0, o);
            float e0 = d0 + sd; e0 = (e0 > 0.f) ? e0 : NEG_SLOPE * e0;
            float w0 = __expf(e0);
            s += w0;
            acc0 = fmaf(w0, f0a, acc0); acc1 = fmaf(w0, f0b, acc1);
            acc2 = fmaf(w0, f0c, acc2); acc3 = fmaf(w0, f0d, acc3);
        }
    }

    float inv = 1.f / s;
    float4 bv = *(const float4*)(bias + lane * 4);
    float r0 = acc0 * inv + bv.x;
    float r1 = acc1 * inv + bv.y;
    float r2 = acc2 * inv + bv.z;
    float r3 = acc3 * inv + bv.w;
    r0 = (r0 > 0.f) ? r0 : expm1f(r0);
    r1 = (r1 > 0.f) ? r1 : expm1f(r1);
    r2 = (r2 > 0.f) ? r2 : expm1f(r2);
    r3 = (r3 > 0.f) ? r3 : expm1f(r3);
    *(float4*)(out + (size_t)node * HID + lane * 4) = make_float4(r0, r1, r2, r3);
}

__global__ void k_aggH(const __half* __restrict__ h,
                       const float* __restrict__ asrc, const float* __restrict__ sdst,
                       const float* __restrict__ bias, float* __restrict__ out) {
    int node = (blockIdx.x * blockDim.x + threadIdx.x) >> 5;
    if (node >= N_NODES) return;
    int lane = threadIdx.x & 31;
    float4 a1v = *(const float4*)(asrc + lane * 4);
    RealColsV cf{g_col};
    aggH_core(node, cf, g_off[node], g_off[node + 1], h, sdst[node], a1v, bias, out, lane);
}

// Probe: identical core on synthetic CSR (deg 17, hashed cols), real h1.
// Writes g_o1 rows [0,N_PROBE) which the real aggH later overwrites.
__global__ void k_probe(const __half* __restrict__ h,
                        const float* __restrict__ asrc, const float* __restrict__ sdst,
                        const float* __restrict__ bias, float* __restrict__ out) {
    int node = (blockIdx.x * blockDim.x + threadIdx.x) >> 5;
    if (node >= N_PROBE) return;
    int lane = threadIdx.x & 31;
    float4 a1v = *(const float4*)(asrc + lane * 4);
    HashColsV cf{(unsigned)node * 2654435761u};
    aggH_core(node, cf, 0, 17, h, sdst[node], a1v, bias, out, lane);
}

// ---------------- agg v4 (layer 2): single-pass plain exp, fp32 F=64 ----------------
__global__ void k_agg64(const float* __restrict__ h,
                        const float* __restrict__ asrc, const float* __restrict__ sdst,
                        const float* __restrict__ bias, float* __restrict__ out) {
    int node = (blockIdx.x * blockDim.x + threadIdx.x) >> 5;
    if (node >= N_NODES) return;
    int lane = threadIdx.x & 31;
    int beg = g_off[node], end = g_off[node + 1];
    float sd = sdst[node];
    float2 a1v = *(const float2*)(asrc + lane * 2);

    float s = 0.f;
    float acc0 = 0.f, acc1 = 0.f;

    for (int c0 = beg; c0 < end; c0 += 32) {
        int n = min(32, end - c0);
        int cs = (lane < n) ? g_col[c0 + lane] : 0;

        int k = 0;
        for (; k + 4 <= n; k += 4) {
            int s0 = __shfl_sync(FULLM, cs, k);
            int s1 = __shfl_sync(FULLM, cs, k + 1);
            int s2 = __shfl_sync(FULLM, cs, k + 2);
            int s3 = __shfl_sync(FULLM, cs, k + 3);
            float2 v0 = *(const float2*)(h + (size_t)s0 * OUTD + lane * 2);
            float2 v1 = *(const float2*)(h + (size_t)s1 * OUTD + lane * 2);
            float2 v2 = *(const float2*)(h + (size_t)s2 * OUTD + lane * 2);
            float2 v3 = *(const float2*)(h + (size_t)s3 * OUTD + lane * 2);
            float d0 = v0.x * a1v.x + v0.y * a1v.y;
            float d1 = v1.x * a1v.x + v1.y * a1v.y;
            float d2 = v2.x * a1v.x + v2.y * a1v.y;
            float d3 = v3.x * a1v.x + v3.y * a1v.y;
            #pragma unroll
            for (int o = 16; o; o >>= 1) {
                d0 += __shfl_xor_sync(FULLM, d0, o);
                d1 += __shfl_xor_sync(FULLM, d1, o);
                d2 += __shfl_xor_sync(FULLM, d2, o);
                d3 += __shfl_xor_sync(FULLM, d3, o);
            }
            float e0 = d0 + sd; e0 = (e0 > 0.f) ? e0 : NEG_SLOPE * e0;
            float e1 = d1 + sd; e1 = (e1 > 0.f) ? e1 : NEG_SLOPE * e1;
            float e2 = d2 + sd; e2 = (e2 > 0.f) ? e2 : NEG_SLOPE * e2;
            float e3 = d3 + sd; e3 = (e3 > 0.f) ? e3 : NEG_SLOPE * e3;
            float w0 = __expf(e0), w1 = __expf(e1), w2 = __expf(e2), w3 = __expf(e3);
            s += (w0 + w1) + (w2 + w3);
            acc0 = fmaf(w0, v0.x, acc0); acc1 = fmaf(w0, v0.y, acc1);
            acc0 = fmaf(w1, v1.x, acc0); acc1 = fmaf(w1, v1.y, acc1);
            acc0 = fmaf(w2, v2.x, acc0); acc1 = fmaf(w2, v2.y, acc1);
            acc0 = fmaf(w3, v3.x, acc0); acc1 = fmaf(w3, v3.y, acc1);
        }
        for (; k < n; k++) {
            int s0 = __shfl_sync(FULLM, cs, k);
            float2 v0 = *(const float2*)(h + (size_t)s0 * OUTD + lane * 2);
            float d0 = v0.x * a1v.x + v0.y * a1v.y;
            #pragma unroll
            for (int o = 16; o; o >>= 1) d0 += __shfl_xor_sync(FULLM, d0, o);
            float e0 = d0 + sd; e0 = (e0 > 0.f) ? e0 : NEG_SLOPE * e0;
            float w0 = __expf(e0);
            s += w0;
            acc0 = fmaf(w0, v0.x, acc0); acc1 = fmaf(w0, v0.y, acc1);
        }
    }

    float inv = 1.f / s;
    float2 bv = *(const float2*)(bias + lane * 2);
    float2 o2 = make_float2(acc0 * inv + bv.x, acc1 * inv + bv.y);
    *(float2*)(out + (size_t)node * OUTD + lane * 2) = o2;
}

// ---------------- final copy (staged result -> d_out), streaming ----------------
__global__ void k_copy(const float* __restrict__ src, float* __restrict__ dst) {
    int i = blockIdx.x * blockDim.x + threadIdx.x;
    if (i < N_NODES * (OUTD / 4)) ((float4*)dst)[i] = ((const float4*)src)[i];
}

// ---------------- launch ----------------
extern "C" void kernel_launch(void* const* d_in, const int* in_sizes, int n_in,
                              void* d_out, int out_size) {
    const float* x   = (const float*)d_in[0];
    const int*   ei  = (const int*)d_in[1];
    const float* W1  = (const float*)d_in[2];
    const float* a1s = (const float*)d_in[3];
    const float* a1d = (const float*)d_in[4];
    const float* b1  = (const float*)d_in[5];
    const float* W2  = (const float*)d_in[6];
    const float* a2s = (const float*)d_in[7];
    const float* a2d = (const float*)d_in[8];
    const float* b2  = (const float*)d_in[9];

    __half* h1h = (__half*)d_out;
    float*  h2  = (float*)d_out;
    float*  out = (float*)d_out;

    const int nodeBlk  = (N_NODES + 255) / 256;
    const int edgeBlk  = (ETOT + 255) / 256;
    const int warpBlk  = (N_NODES * 32 + 255) / 256;
    const int probeBlk = (N_PROBE * 32 + 255) / 256;
    const int gBlk     = (N_NODES + 63) / 64;
    const int cpBlk    = (N_NODES * (OUTD / 4) + 255) / 256;

    k_zeroA<<<nodeBlk, 256>>>();                                             // 0
    k_count<<<edgeBlk, 256>>>(ei);                                           // 1
    k_gemm1_mma<<<gBlk, 256>>>(x, W1, h1h, a1s, a1d,
                               g_ssrc, g_sdst, N_NODES);                     // 2
    k_probe<<<probeBlk, 256>>>(h1h, a1s, g_sdst, b1, g_o1);                  // 3 <- ncu
    k_zeroB<<<nodeBlk, 256>>>();                                             // 4
    k_scan1<<<SCAN_NB, 256>>>();                                             // 5
    k_scan2<<<1, 512>>>(SCAN_NB);                                            // 6
    k_scan3<<<SCAN_NB, 256>>>();                                             // 7
    k_fill<<<edgeBlk, 256>>>(ei);                                            // 8
    k_aggH<<<warpBlk, 256>>>(h1h, a1s, g_sdst, b1, g_o1);                    // 9
    k_gemm2_mma<<<gBlk, 256>>>(g_o1, W2, h2, a2s, a2d,
                               g_ssrc, g_sdst, N_NODES);                     // 10
    k_agg64<<<warpBlk, 256>>>(h2, a2s, g_sdst, b2, g_o2);                    // 11
    k_copy<<<cpBlk, 256>>>(g_o2, out);                                       // 12
}

// round 16
// speedup vs baseline: 1.2996x; 1.2996x over previous
#include <cuda_runtime.h>
#include <cuda_fp16.h>
#include <math.h>
#include <float.h>

#define N_NODES 100000
#define N_EDGES 1600000
#define ETOT    (N_EDGES + N_NODES)
#define IN_DIM  256
#define HID     128
#define OUTD    64
#define NEG_SLOPE 0.2f
#define SCAN_NB ((N_NODES + 255) / 256)   // 391
#define FULLM 0xffffffffu

// ---------------- scratch (static device globals; no allocation) ----------------
// Measured law: ALL static (host-resident, C2C) traffic ~200GB/s; random access
// pays 32B sector amplification. Gather tables live in d_out (device).
// o1 staged fp16 (halves the C2C round trip; numerically identical since gemm2
// converts to fp16 anyway).
static __device__ __align__(128) __half g_o1h[(size_t)N_NODES * HID]; // 25.6MB streamed
static __device__ __align__(128) float  g_o2[(size_t)N_NODES * OUTD]; // streamed
static __device__ float g_ssrc[N_NODES];
static __device__ float g_sdst[N_NODES];
static __device__ int   g_cnt[N_NODES];
static __device__ int   g_cur[N_NODES];
static __device__ int   g_off[N_NODES + 1];
static __device__ int   g_bsum[512];
static __device__ int   g_col[ETOT];

// ---------------- CSR build (verbatim, verified) ----------------
__global__ void k_zeroA() {
    int i = blockIdx.x * blockDim.x + threadIdx.x;
    if (i < N_NODES) g_cnt[i] = 0;
}
__global__ void k_zeroB() {
    int i = blockIdx.x * blockDim.x + threadIdx.x;
    if (i < N_NODES) g_cur[i] = 0;
}

__global__ void k_count(const int* __restrict__ ei) {
    int t = blockIdx.x * blockDim.x + threadIdx.x;
    if (t >= ETOT) return;
    int dst = (t < N_EDGES) ? ei[N_EDGES + t] : (t - N_EDGES);
    atomicAdd(&g_cnt[dst], 1);
}

__global__ void k_scan1() {
    __shared__ int s[256];
    int t = threadIdx.x, idx = blockIdx.x * 256 + t;
    int v = (idx < N_NODES) ? g_cnt[idx] : 0;
    s[t] = v; __syncthreads();
    #pragma unroll
    for (int o = 1; o < 256; o <<= 1) {
        int u = (t >= o) ? s[t - o] : 0;
        __syncthreads();
        s[t] += u;
        __syncthreads();
    }
    if (idx < N_NODES) g_off[idx] = s[t] - v;
    if (t == 255) g_bsum[blockIdx.x] = s[t];
}

__global__ void k_scan2(int nb) {
    __shared__ int s[512];
    int t = threadIdx.x;
    int v = (t < nb) ? g_bsum[t] : 0;
    s[t] = v; __syncthreads();
    #pragma unroll
    for (int o = 1; o < 512; o <<= 1) {
        int u = (t >= o) ? s[t - o] : 0;
        __syncthreads();
        s[t] += u;
        __syncthreads();
    }
    g_bsum[t] = s[t] - v;
}

__global__ void k_scan3() {
    int t = threadIdx.x, idx = blockIdx.x * 256 + t;
    if (idx < N_NODES) g_off[idx] += g_bsum[blockIdx.x];
    if (idx == 0) g_off[N_NODES] = ETOT;
}

__global__ void k_fill(const int* __restrict__ ei) {
    int t = blockIdx.x * blockDim.x + threadIdx.x;
    if (t >= ETOT) return;
    int src, dst;
    if (t < N_EDGES) { src = ei[t]; dst = ei[N_EDGES + t]; }
    else             { src = dst = t - N_EDGES; }
    int pos = g_off[dst] + atomicAdd(&g_cur[dst], 1);
    g_col[pos] = src;
}

// ---------------- tensor-core GEMM1 (verbatim, verified) ----------------
__global__ void __launch_bounds__(256) k_gemm1_mma(
        const float* __restrict__ A, const float* __restrict__ W,
        __half* __restrict__ Hout,
        const float* __restrict__ asrc, const float* __restrict__ adst,
        float* __restrict__ ssrc, float* __restrict__ sdst, int M) {
    constexpr int BM = 64;
    __shared__ __half As[BM][24];
    __shared__ __half Bs[128][20];
    __shared__ __half Hs[BM][136];

    const int tid = threadIdx.x;
    const int w   = tid >> 5;
    const int lane = tid & 31;
    const int g = lane >> 2;
    const int t = lane & 3;
    const int wm = (w & 1) * 32;
    const int wn = (w >> 1) * 32;
    const int m0 = blockIdx.x * BM;

    float c[2][4][4];
    #pragma unroll
    for (int mf = 0; mf < 2; mf++)
        #pragma unroll
        for (int nf = 0; nf < 4; nf++)
            #pragma unroll
            for (int q = 0; q < 4; q++) c[mf][nf][q] = 0.f;

    const int arow = tid >> 2;
    const int ac4  = (tid & 3) * 4;

    for (int k0 = 0; k0 < IN_DIM; k0 += 16) {
        {
            float4 v = make_float4(0.f, 0.f, 0.f, 0.f);
            int gr = m0 + arow;
            if (gr < M) v = *(const float4*)(A + (size_t)gr * IN_DIM + k0 + ac4);
            *(__half2*)&As[arow][ac4]     = __floats2half2_rn(v.x, v.y);
            *(__half2*)&As[arow][ac4 + 2] = __floats2half2_rn(v.z, v.w);
        }
        #pragma unroll
        for (int i = tid; i < 16 * 32; i += 256) {
            int kk = i >> 5;
            int n4 = (i & 31) * 4;
            float4 wv = *(const float4*)(W + (size_t)(k0 + kk) * HID + n4);
            Bs[n4 + 0][kk] = __float2half_rn(wv.x);
            Bs[n4 + 1][kk] = __float2half_rn(wv.y);
            Bs[n4 + 2][kk] = __float2half_rn(wv.z);
            Bs[n4 + 3][kk] = __float2half_rn(wv.w);
        }
        __syncthreads();

        unsigned a[2][4];
        #pragma unroll
        for (int mf = 0; mf < 2; mf++) {
            int r = wm + mf * 16;
            a[mf][0] = *(const unsigned*)&As[r + g][2 * t];
            a[mf][1] = *(const unsigned*)&As[r + 8 + g][2 * t];
            a[mf][2] = *(const unsigned*)&As[r + g][2 * t + 8];
            a[mf][3] = *(const unsigned*)&As[r + 8 + g][2 * t + 8];
        }
        #pragma unroll
        for (int nf = 0; nf < 4; nf++) {
            int n = wn + nf * 8;
            unsigned b0 = *(const unsigned*)&Bs[n + g][2 * t];
            unsigned b1 = *(const unsigned*)&Bs[n + g][2 * t + 8];
            #pragma unroll
            for (int mf = 0; mf < 2; mf++) {
                asm volatile(
                    "mma.sync.aligned.m16n8k16.row.col.f32.f16.f16.f32 "
                    "{%0,%1,%2,%3}, {%4,%5,%6,%7}, {%8,%9}, {%0,%1,%2,%3};"
                    : "+f"(c[mf][nf][0]), "+f"(c[mf][nf][1]),
                      "+f"(c[mf][nf][2]), "+f"(c[mf][nf][3])
                    : "r"(a[mf][0]), "r"(a[mf][1]), "r"(a[mf][2]), "r"(a[mf][3]),
                      "r"(b0), "r"(b1));
            }
        }
        __syncthreads();
    }

    #pragma unroll
    for (int mf = 0; mf < 2; mf++) {
        #pragma unroll
        for (int nf = 0; nf < 4; nf++) {
            int r0 = wm + mf * 16 + g;
            int cc = wn + nf * 8 + 2 * t;
            *(__half2*)&Hs[r0][cc]     = __floats2half2_rn(c[mf][nf][0], c[mf][nf][1]);
            *(__half2*)&Hs[r0 + 8][cc] = __floats2half2_rn(c[mf][nf][2], c[mf][nf][3]);
        }
    }
    __syncthreads();

    #pragma unroll
    for (int i = tid; i < 64 * 16; i += 256) {
        int row = i >> 4, seg = i & 15;
        if (m0 + row < M) {
            uint4 v = *(const uint4*)&Hs[row][seg * 8];
            *(uint4*)(Hout + (size_t)(m0 + row) * HID + seg * 8) = v;
        }
    }

    float4 a1v = *(const float4*)(asrc + lane * 4);
    float4 a2v = *(const float4*)(adst + lane * 4);
    #pragma unroll
    for (int r = 0; r < 8; r++) {
        int row = w * 8 + r;
        uint2 hv = *(const uint2*)&Hs[row][lane * 4];
        const __half* hp = reinterpret_cast<const __half*>(&hv);
        float f0 = __half2float(hp[0]), f1 = __half2float(hp[1]);
        float f2 = __half2float(hp[2]), f3 = __half2float(hp[3]);
        float d1 = f0 * a1v.x + f1 * a1v.y + f2 * a1v.z + f3 * a1v.w;
        float d2 = f0 * a2v.x + f1 * a2v.y + f2 * a2v.z + f3 * a2v.w;
        #pragma unroll
        for (int o = 16; o; o >>= 1) {
            d1 += __shfl_xor_sync(FULLM, d1, o);
            d2 += __shfl_xor_sync(FULLM, d2, o);
        }
        if (lane == 0 && m0 + row < M) {
            ssrc[m0 + row] = d1;
            sdst[m0 + row] = d2;
        }
    }
}

// ---------------- tensor-core GEMM2, fp16 A operand (o1 staged fp16) ----------------
__global__ void __launch_bounds__(256) k_gemm2_mma(
        const __half* __restrict__ A16, const float* __restrict__ W,
        float* __restrict__ Hout,
        const float* __restrict__ asrc, const float* __restrict__ adst,
        float* __restrict__ ssrc, float* __restrict__ sdst, int M) {
    constexpr int BM = 64;
    __shared__ __half As[BM][24];
    __shared__ __half Bs[64][20];
    __shared__ float  Hs[BM][68];

    const int tid = threadIdx.x;
    const int w   = tid >> 5;
    const int lane = tid & 31;
    const int g = lane >> 2;
    const int t = lane & 3;
    const int wm = (w & 3) * 16;
    const int wn = (w >> 2) * 32;
    const int m0 = blockIdx.x * BM;

    float c[4][4];
    #pragma unroll
    for (int nf = 0; nf < 4; nf++)
        #pragma unroll
        for (int q = 0; q < 4; q++) c[nf][q] = 0.f;

    const int arow = tid >> 2;
    const int ac4  = (tid & 3) * 4;

    for (int k0 = 0; k0 < HID; k0 += 16) {
        {
            uint2 v = make_uint2(0u, 0u);     // 4 halves
            int gr = m0 + arow;
            if (gr < M) v = *(const uint2*)(A16 + (size_t)gr * HID + k0 + ac4);
            *(uint2*)&As[arow][ac4] = v;
        }
        {
            int kk = tid >> 4;
            int n4 = (tid & 15) * 4;
            float4 wv = *(const float4*)(W + (size_t)(k0 + kk) * OUTD + n4);
            Bs[n4 + 0][kk] = __float2half_rn(wv.x);
            Bs[n4 + 1][kk] = __float2half_rn(wv.y);
            Bs[n4 + 2][kk] = __float2half_rn(wv.z);
            Bs[n4 + 3][kk] = __float2half_rn(wv.w);
        }
        __syncthreads();

        unsigned a[4];
        a[0] = *(const unsigned*)&As[wm + g][2 * t];
        a[1] = *(const unsigned*)&As[wm + 8 + g][2 * t];
        a[2] = *(const unsigned*)&As[wm + g][2 * t + 8];
        a[3] = *(const unsigned*)&As[wm + 8 + g][2 * t + 8];
        #pragma unroll
        for (int nf = 0; nf < 4; nf++) {
            int n = wn + nf * 8;
            unsigned b0 = *(const unsigned*)&Bs[n + g][2 * t];
            unsigned b1 = *(const unsigned*)&Bs[n + g][2 * t + 8];
            asm volatile(
                "mma.sync.aligned.m16n8k16.row.col.f32.f16.f16.f32 "
                "{%0,%1,%2,%3}, {%4,%5,%6,%7}, {%8,%9}, {%0,%1,%2,%3};"
                : "+f"(c[nf][0]), "+f"(c[nf][1]), "+f"(c[nf][2]), "+f"(c[nf][3])
                : "r"(a[0]), "r"(a[1]), "r"(a[2]), "r"(a[3]),
                  "r"(b0), "r"(b1));
        }
        __syncthreads();
    }

    #pragma unroll
    for (int nf = 0; nf < 4; nf++) {
        int cc = wn + nf * 8 + 2 * t;
        Hs[wm + g][cc]     = c[nf][0];
        Hs[wm + g][cc + 1] = c[nf][1];
        Hs[wm + 8 + g][cc]     = c[nf][2];
        Hs[wm + 8 + g][cc + 1] = c[nf][3];
    }
    __syncthreads();

    #pragma unroll
    for (int i = tid; i < 64 * 16; i += 256) {
        int row = i >> 4, seg = (i & 15) * 4;
        if (m0 + row < M) {
            float4 v = *(const float4*)&Hs[row][seg];
            *(float4*)(Hout + (size_t)(m0 + row) * OUTD + seg) = v;
        }
    }

    float2 a1v = *(const float2*)(asrc + lane * 2);
    float2 a2v = *(const float2*)(adst + lane * 2);
    #pragma unroll
    for (int r = 0; r < 8; r++) {
        int row = w * 8 + r;
        float2 hv = *(const float2*)&Hs[row][lane * 2];
        float d1 = hv.x * a1v.x + hv.y * a1v.y;
        float d2 = hv.x * a2v.x + hv.y * a2v.y;
        #pragma unroll
        for (int o = 16; o; o >>= 1) {
            d1 += __shfl_xor_sync(FULLM, d1, o);
            d2 += __shfl_xor_sync(FULLM, d2, o);
        }
        if (lane == 0 && m0 + row < M) {
            ssrc[m0 + row] = d1;
            sdst[m0 + row] = d2;
        }
    }
}

// ---------------- layer-1 agg (R14 verified body; output stored as fp16) --------
__global__ void k_aggH(const __half* __restrict__ h,
                       const float* __restrict__ asrc, const float* __restrict__ sdst,
                       const float* __restrict__ bias, __half* __restrict__ out) {
    int node = (blockIdx.x * blockDim.x + threadIdx.x) >> 5;
    if (node >= N_NODES) return;
    int lane = threadIdx.x & 31;
    int beg = g_off[node], end = g_off[node + 1];
    float sd = sdst[node];
    float4 a1v = *(const float4*)(asrc + lane * 4);

    float m = -FLT_MAX, s = 0.f;
    float acc0 = 0.f, acc1 = 0.f, acc2 = 0.f, acc3 = 0.f;

    for (int c0 = beg; c0 < end; c0 += 32) {
        int n = min(32, end - c0);
        int cs = (lane < n) ? g_col[c0 + lane] : 0;

        int k = 0;
        for (; k + 4 <= n; k += 4) {
            int s0 = __shfl_sync(FULLM, cs, k);
            int s1 = __shfl_sync(FULLM, cs, k + 1);
            int s2 = __shfl_sync(FULLM, cs, k + 2);
            int s3 = __shfl_sync(FULLM, cs, k + 3);
            uint2 r0 = *(const uint2*)(h + (size_t)s0 * HID + lane * 4);
            uint2 r1 = *(const uint2*)(h + (size_t)s1 * HID + lane * 4);
            uint2 r2 = *(const uint2*)(h + (size_t)s2 * HID + lane * 4);
            uint2 r3 = *(const uint2*)(h + (size_t)s3 * HID + lane * 4);
            const __half* p0 = reinterpret_cast<const __half*>(&r0);
            const __half* p1 = reinterpret_cast<const __half*>(&r1);
            const __half* p2 = reinterpret_cast<const __half*>(&r2);
            const __half* p3 = reinterpret_cast<const __half*>(&r3);
            float f0a = __half2float(p0[0]), f0b = __half2float(p0[1]),
                  f0c = __half2float(p0[2]), f0d = __half2float(p0[3]);
            float f1a = __half2float(p1[0]), f1b = __half2float(p1[1]),
                  f1c = __half2float(p1[2]), f1d = __half2float(p1[3]);
            float f2a = __half2float(p2[0]), f2b = __half2float(p2[1]),
                  f2c = __half2float(p2[2]), f2d = __half2float(p2[3]);
            float f3a = __half2float(p3[0]), f3b = __half2float(p3[1]),
                  f3c = __half2float(p3[2]), f3d = __half2float(p3[3]);
            float d0 = f0a * a1v.x + f0b * a1v.y + f0c * a1v.z + f0d * a1v.w;
            float d1 = f1a * a1v.x + f1b * a1v.y + f1c * a1v.z + f1d * a1v.w;
            float d2 = f2a * a1v.x + f2b * a1v.y + f2c * a1v.z + f2d * a1v.w;
            float d3 = f3a * a1v.x + f3b * a1v.y + f3c * a1v.z + f3d * a1v.w;
            #pragma unroll
            for (int o = 16; o; o >>= 1) {
                d0 += __shfl_xor_sync(FULLM, d0, o);
                d1 += __shfl_xor_sync(FULLM, d1, o);
                d2 += __shfl_xor_sync(FULLM, d2, o);
                d3 += __shfl_xor_sync(FULLM, d3, o);
            }
            float e, mn, sc, wt;
            e = d0 + sd; e = (e > 0.f) ? e : NEG_SLOPE * e;
            mn = fmaxf(m, e); sc = __expf(m - mn); wt = __expf(e - mn);
            s = s * sc + wt;
            acc0 = acc0 * sc + wt * f0a; acc1 = acc1 * sc + wt * f0b;
            acc2 = acc2 * sc + wt * f0c; acc3 = acc3 * sc + wt * f0d;
            m = mn;
            e = d1 + sd; e = (e > 0.f) ? e : NEG_SLOPE * e;
            mn = fmaxf(m, e); sc = __expf(m - mn); wt = __expf(e - mn);
            s = s * sc + wt;
            acc0 = acc0 * sc + wt * f1a; acc1 = acc1 * sc + wt * f1b;
            acc2 = acc2 * sc + wt * f1c; acc3 = acc3 * sc + wt * f1d;
            m = mn;
            e = d2 + sd; e = (e > 0.f) ? e : NEG_SLOPE * e;
            mn = fmaxf(m, e); sc = __expf(m - mn); wt = __expf(e - mn);
            s = s * sc + wt;
            acc0 = acc0 * sc + wt * f2a; acc1 = acc1 * sc + wt * f2b;
            acc2 = acc2 * sc + wt * f2c; acc3 = acc3 * sc + wt * f2d;
            m = mn;
            e = d3 + sd; e = (e > 0.f) ? e : NEG_SLOPE * e;
            mn = fmaxf(m, e); sc = __expf(m - mn); wt = __expf(e - mn);
            s = s * sc + wt;
            acc0 = acc0 * sc + wt * f3a; acc1 = acc1 * sc + wt * f3b;
            acc2 = acc2 * sc + wt * f3c; acc3 = acc3 * sc + wt * f3d;
            m = mn;
        }
        for (; k < n; k++) {
            int s0 = __shfl_sync(FULLM, cs, k);
            uint2 r0 = *(const uint2*)(h + (size_t)s0 * HID + lane * 4);
            const __half* p0 = reinterpret_cast<const __half*>(&r0);
            float f0a = __half2float(p0[0]), f0b = __half2float(p0[1]),
                  f0c = __half2float(p0[2]), f0d = __half2float(p0[3]);
            float d0 = f0a * a1v.x + f0b * a1v.y + f0c * a1v.z + f0d * a1v.w;
            #pragma unroll
            for (int o = 16; o; o >>= 1) d0 += __shfl_xor_sync(FULLM, d0, o);
            float e = d0 + sd; e = (e > 0.f) ? e : NEG_SLOPE * e;
            float mn = fmaxf(m, e);
            float sc = __expf(m - mn);
            float wt = __expf(e - mn);
            s = s * sc + wt;
            acc0 = acc0 * sc + wt * f0a; acc1 = acc1 * sc + wt * f0b;
            acc2 = acc2 * sc + wt * f0c; acc3 = acc3 * sc + wt * f0d;
            m = mn;
        }
    }

    float inv = 1.f / s;
    float4 bv = *(const float4*)(bias + lane * 4);
    float r0 = acc0 * inv + bv.x;
    float r1 = acc1 * inv + bv.y;
    float r2 = acc2 * inv + bv.z;
    float r3 = acc3 * inv + bv.w;
    r0 = (r0 > 0.f) ? r0 : expm1f(r0);
    r1 = (r1 > 0.f) ? r1 : expm1f(r1);
    r2 = (r2 > 0.f) ? r2 : expm1f(r2);
    r3 = (r3 > 0.f) ? r3 : expm1f(r3);
    __half2 ha = __floats2half2_rn(r0, r1);
    __half2 hb = __floats2half2_rn(r2, r3);
    uint2 u;
    u.x = *(unsigned*)&ha;
    u.y = *(unsigned*)&hb;
    *(uint2*)(out + (size_t)node * HID + lane * 4) = u;
}

// ---------------- layer-2 agg (R14 verified body, fp32 F=64) ----------------
__global__ void k_agg64(const float* __restrict__ h,
                        const float* __restrict__ asrc, const float* __restrict__ sdst,
                        const float* __restrict__ bias, float* __restrict__ out) {
    int node = (blockIdx.x * blockDim.x + threadIdx.x) >> 5;
    if (node >= N_NODES) return;
    int lane = threadIdx.x & 31;
    int beg = g_off[node], end = g_off[node + 1];
    float sd = sdst[node];
    float2 a1v = *(const float2*)(asrc + lane * 2);

    float m = -FLT_MAX, s = 0.f;
    float acc0 = 0.f, acc1 = 0.f;

    for (int c0 = beg; c0 < end; c0 += 32) {
        int n = min(32, end - c0);
        int cs = (lane < n) ? g_col[c0 + lane] : 0;

        int k = 0;
        for (; k + 4 <= n; k += 4) {
            int s0 = __shfl_sync(FULLM, cs, k);
            int s1 = __shfl_sync(FULLM, cs, k + 1);
            int s2 = __shfl_sync(FULLM, cs, k + 2);
            int s3 = __shfl_sync(FULLM, cs, k + 3);
            float2 v0 = *(const float2*)(h + (size_t)s0 * OUTD + lane * 2);
            float2 v1 = *(const float2*)(h + (size_t)s1 * OUTD + lane * 2);
            float2 v2 = *(const float2*)(h + (size_t)s2 * OUTD + lane * 2);
            float2 v3 = *(const float2*)(h + (size_t)s3 * OUTD + lane * 2);
            float d0 = v0.x * a1v.x + v0.y * a1v.y;
            float d1 = v1.x * a1v.x + v1.y * a1v.y;
            float d2 = v2.x * a1v.x + v2.y * a1v.y;
            float d3 = v3.x * a1v.x + v3.y * a1v.y;
            #pragma unroll
            for (int o = 16; o; o >>= 1) {
                d0 += __shfl_xor_sync(FULLM, d0, o);
                d1 += __shfl_xor_sync(FULLM, d1, o);
                d2 += __shfl_xor_sync(FULLM, d2, o);
                d3 += __shfl_xor_sync(FULLM, d3, o);
            }
            float e, mn, sc, wt;
            e = d0 + sd; e = (e > 0.f) ? e : NEG_SLOPE * e;
            mn = fmaxf(m, e); sc = __expf(m - mn); wt = __expf(e - mn);
            s = s * sc + wt;
            acc0 = acc0 * sc + wt * v0.x; acc1 = acc1 * sc + wt * v0.y;
            m = mn;
            e = d1 + sd; e = (e > 0.f) ? e : NEG_SLOPE * e;
            mn = fmaxf(m, e); sc = __expf(m - mn); wt = __expf(e - mn);
            s = s * sc + wt;
            acc0 = acc0 * sc + wt * v1.x; acc1 = acc1 * sc + wt * v1.y;
            m = mn;
            e = d2 + sd; e = (e > 0.f) ? e : NEG_SLOPE * e;
            mn = fmaxf(m, e); sc = __expf(m - mn); wt = __expf(e - mn);
            s = s * sc + wt;
            acc0 = acc0 * sc + wt * v2.x; acc1 = acc1 * sc + wt * v2.y;
            m = mn;
            e = d3 + sd; e = (e > 0.f) ? e : NEG_SLOPE * e;
            mn = fmaxf(m, e); sc = __expf(m - mn); wt = __expf(e - mn);
            s = s * sc + wt;
            acc0 = acc0 * sc + wt * v3.x; acc1 = acc1 * sc + wt * v3.y;
            m = mn;
        }
        for (; k < n; k++) {
            int s0 = __shfl_sync(FULLM, cs, k);
            float2 v0 = *(const float2*)(h + (size_t)s0 * OUTD + lane * 2);
            float d0 = v0.x * a1v.x + v0.y * a1v.y;
            #pragma unroll
            for (int o = 16; o; o >>= 1) d0 += __shfl_xor_sync(FULLM, d0, o);
            float e = d0 + sd; e = (e > 0.f) ? e : NEG_SLOPE * e;
            float mn = fmaxf(m, e);
            float sc = __expf(m - mn);
            float wt = __expf(e - mn);
            s = s * sc + wt;
            acc0 = acc0 * sc + wt * v0.x; acc1 = acc1 * sc + wt * v0.y;
            m = mn;
        }
    }

    float inv = 1.f / s;
    float2 bv = *(const float2*)(bias + lane * 2);
    float2 o2 = make_float2(acc0 * inv + bv.x, acc1 * inv + bv.y);
    *(float2*)(out + (size_t)node * OUTD + lane * 2) = o2;
}

// ---------------- final copy (staged result -> d_out), streaming ----------------
__global__ void k_copy(const float* __restrict__ src, float* __restrict__ dst) {
    int i = blockIdx.x * blockDim.x + threadIdx.x;
    if (i < N_NODES * (OUTD / 4)) ((float4*)dst)[i] = ((const float4*)src)[i];
}

// ---------------- launch ----------------
extern "C" void kernel_launch(void* const* d_in, const int* in_sizes, int n_in,
                              void* d_out, int out_size) {
    const float* x   = (const float*)d_in[0];
    const int*   ei  = (const int*)d_in[1];
    const float* W1  = (const float*)d_in[2];
    const float* a1s = (const float*)d_in[3];
    const float* a1d = (const float*)d_in[4];
    const float* b1  = (const float*)d_in[5];
    const float* W2  = (const float*)d_in[6];
    const float* a2s = (const float*)d_in[7];
    const float* a2d = (const float*)d_in[8];
    const float* b2  = (const float*)d_in[9];

    __half* h1h = (__half*)d_out;
    float*  h2  = (float*)d_out;
    float*  out = (float*)d_out;

    const int nodeBlk = (N_NODES + 255) / 256;
    const int edgeBlk = (ETOT + 255) / 256;
    const int warpBlk = (N_NODES * 32 + 255) / 256;
    const int gBlk    = (N_NODES + 63) / 64;
    const int cpBlk   = (N_NODES * (OUTD / 4) + 255) / 256;

    k_zeroA<<<nodeBlk, 256>>>();                                             // 0
    k_count<<<edgeBlk, 256>>>(ei);                                           // 1
    k_zeroB<<<nodeBlk, 256>>>();                                             // 2
    k_gemm1_mma<<<gBlk, 256>>>(x, W1, h1h, a1s, a1d,
                               g_ssrc, g_sdst, N_NODES);                     // 3 <- ncu
    k_scan1<<<SCAN_NB, 256>>>();                                             // 4
    k_scan2<<<1, 512>>>(SCAN_NB);                                            // 5
    k_scan3<<<SCAN_NB, 256>>>();                                             // 6
    k_fill<<<edgeBlk, 256>>>(ei);                                            // 7
    k_aggH<<<warpBlk, 256>>>(h1h, a1s, g_sdst, b1, g_o1h);                   // 8
    k_gemm2_mma<<<gBlk, 256>>>(g_o1h, W2, h2, a2s, a2d,
                               g_ssrc, g_sdst, N_NODES);                     // 9
    k_agg64<<<warpBlk, 256>>>(h2, a2s, g_sdst, b2, g_o2);                    // 10
    k_copy<<<cpBlk, 256>>>(g_o2, out);                                       // 11
}

// round 17
// speedup vs baseline: 1.7000x; 1.3082x over previous
#include <cuda_runtime.h>
#include <cuda_fp16.h>
#include <math.h>
#include <float.h>

#define N_NODES 100000
#define N_HALF  (N_NODES / 2)
#define N_EDGES 1600000
#define ETOT    (N_EDGES + N_NODES)
#define IN_DIM  256
#define HID     128
#define OUTD    64
#define NEG_SLOPE 0.2f
#define SCAN_NB ((N_NODES + 255) / 256)   // 391
#define FULLM 0xffffffffu

// ---------------- scratch (static device globals; no allocation) ----------------
// Law: all static traffic crosses C2C @~200GB/s. d_out (25.6MB device) is the
// only gather-capable memory. Staging minimized: h2 fp16 (12.8MB), o2b (12.8MB).
static __device__ __align__(128) __half g_h2h[(size_t)N_NODES * OUTD];   // 12.8MB
static __device__ __align__(128) float  g_o2b[(size_t)N_HALF * OUTD];    // 12.8MB
static __device__ float g_ssrc[N_NODES];
static __device__ float g_sdst[N_NODES];
static __device__ int   g_cnt[N_NODES];
static __device__ int   g_cur[N_NODES];
static __device__ int   g_off[N_NODES + 1];
static __device__ int   g_bsum[512];
static __device__ int   g_col[ETOT];

// ---------------- CSR build (verbatim, verified) ----------------
__global__ void k_zeroA() {
    int i = blockIdx.x * blockDim.x + threadIdx.x;
    if (i < N_NODES) g_cnt[i] = 0;
}
__global__ void k_zeroB() {
    int i = blockIdx.x * blockDim.x + threadIdx.x;
    if (i < N_NODES) g_cur[i] = 0;
}

__global__ void k_count(const int* __restrict__ ei) {
    int t = blockIdx.x * blockDim.x + threadIdx.x;
    if (t >= ETOT) return;
    int dst = (t < N_EDGES) ? ei[N_EDGES + t] : (t - N_EDGES);
    atomicAdd(&g_cnt[dst], 1);
}

__global__ void k_scan1() {
    __shared__ int s[256];
    int t = threadIdx.x, idx = blockIdx.x * 256 + t;
    int v = (idx < N_NODES) ? g_cnt[idx] : 0;
    s[t] = v; __syncthreads();
    #pragma unroll
    for (int o = 1; o < 256; o <<= 1) {
        int u = (t >= o) ? s[t - o] : 0;
        __syncthreads();
        s[t] += u;
        __syncthreads();
    }
    if (idx < N_NODES) g_off[idx] = s[t] - v;
    if (t == 255) g_bsum[blockIdx.x] = s[t];
}

__global__ void k_scan2(int nb) {
    __shared__ int s[512];
    int t = threadIdx.x;
    int v = (t < nb) ? g_bsum[t] : 0;
    s[t] = v; __syncthreads();
    #pragma unroll
    for (int o = 1; o < 512; o <<= 1) {
        int u = (t >= o) ? s[t - o] : 0;
        __syncthreads();
        s[t] += u;
        __syncthreads();
    }
    g_bsum[t] = s[t] - v;
}

__global__ void k_scan3() {
    int t = threadIdx.x, idx = blockIdx.x * 256 + t;
    if (idx < N_NODES) g_off[idx] += g_bsum[blockIdx.x];
    if (idx == 0) g_off[N_NODES] = ETOT;
}

__global__ void k_fill(const int* __restrict__ ei) {
    int t = blockIdx.x * blockDim.x + threadIdx.x;
    if (t >= ETOT) return;
    int src, dst;
    if (t < N_EDGES) { src = ei[t]; dst = ei[N_EDGES + t]; }
    else             { src = dst = t - N_EDGES; }
    int pos = g_off[dst] + atomicAdd(&g_cur[dst], 1);
    g_col[pos] = src;
}

// ---------------- tensor-core GEMM1 (verbatim, verified) ----------------
__global__ void __launch_bounds__(256) k_gemm1_mma(
        const float* __restrict__ A, const float* __restrict__ W,
        __half* __restrict__ Hout,
        const float* __restrict__ asrc, const float* __restrict__ adst,
        float* __restrict__ ssrc, float* __restrict__ sdst, int M) {
    constexpr int BM = 64;
    __shared__ __half As[BM][24];
    __shared__ __half Bs[128][20];
    __shared__ __half Hs[BM][136];

    const int tid = threadIdx.x;
    const int w   = tid >> 5;
    const int lane = tid & 31;
    const int g = lane >> 2;
    const int t = lane & 3;
    const int wm = (w & 1) * 32;
    const int wn = (w >> 1) * 32;
    const int m0 = blockIdx.x * BM;

    float c[2][4][4];
    #pragma unroll
    for (int mf = 0; mf < 2; mf++)
        #pragma unroll
        for (int nf = 0; nf < 4; nf++)
            #pragma unroll
            for (int q = 0; q < 4; q++) c[mf][nf][q] = 0.f;

    const int arow = tid >> 2;
    const int ac4  = (tid & 3) * 4;

    for (int k0 = 0; k0 < IN_DIM; k0 += 16) {
        {
            float4 v = make_float4(0.f, 0.f, 0.f, 0.f);
            int gr = m0 + arow;
            if (gr < M) v = *(const float4*)(A + (size_t)gr * IN_DIM + k0 + ac4);
            *(__half2*)&As[arow][ac4]     = __floats2half2_rn(v.x, v.y);
            *(__half2*)&As[arow][ac4 + 2] = __floats2half2_rn(v.z, v.w);
        }
        #pragma unroll
        for (int i = tid; i < 16 * 32; i += 256) {
            int kk = i >> 5;
            int n4 = (i & 31) * 4;
            float4 wv = *(const float4*)(W + (size_t)(k0 + kk) * HID + n4);
            Bs[n4 + 0][kk] = __float2half_rn(wv.x);
            Bs[n4 + 1][kk] = __float2half_rn(wv.y);
            Bs[n4 + 2][kk] = __float2half_rn(wv.z);
            Bs[n4 + 3][kk] = __float2half_rn(wv.w);
        }
        __syncthreads();

        unsigned a[2][4];
        #pragma unroll
        for (int mf = 0; mf < 2; mf++) {
            int r = wm + mf * 16;
            a[mf][0] = *(const unsigned*)&As[r + g][2 * t];
            a[mf][1] = *(const unsigned*)&As[r + 8 + g][2 * t];
            a[mf][2] = *(const unsigned*)&As[r + g][2 * t + 8];
            a[mf][3] = *(const unsigned*)&As[r + 8 + g][2 * t + 8];
        }
        #pragma unroll
        for (int nf = 0; nf < 4; nf++) {
            int n = wn + nf * 8;
            unsigned b0 = *(const unsigned*)&Bs[n + g][2 * t];
            unsigned b1 = *(const unsigned*)&Bs[n + g][2 * t + 8];
            #pragma unroll
            for (int mf = 0; mf < 2; mf++) {
                asm volatile(
                    "mma.sync.aligned.m16n8k16.row.col.f32.f16.f16.f32 "
                    "{%0,%1,%2,%3}, {%4,%5,%6,%7}, {%8,%9}, {%0,%1,%2,%3};"
                    : "+f"(c[mf][nf][0]), "+f"(c[mf][nf][1]),
                      "+f"(c[mf][nf][2]), "+f"(c[mf][nf][3])
                    : "r"(a[mf][0]), "r"(a[mf][1]), "r"(a[mf][2]), "r"(a[mf][3]),
                      "r"(b0), "r"(b1));
            }
        }
        __syncthreads();
    }

    #pragma unroll
    for (int mf = 0; mf < 2; mf++) {
        #pragma unroll
        for (int nf = 0; nf < 4; nf++) {
            int r0 = wm + mf * 16 + g;
            int cc = wn + nf * 8 + 2 * t;
            *(__half2*)&Hs[r0][cc]     = __floats2half2_rn(c[mf][nf][0], c[mf][nf][1]);
            *(__half2*)&Hs[r0 + 8][cc] = __floats2half2_rn(c[mf][nf][2], c[mf][nf][3]);
        }
    }
    __syncthreads();

    #pragma unroll
    for (int i = tid; i < 64 * 16; i += 256) {
        int row = i >> 4, seg = i & 15;
        if (m0 + row < M) {
            uint4 v = *(const uint4*)&Hs[row][seg * 8];
            *(uint4*)(Hout + (size_t)(m0 + row) * HID + seg * 8) = v;
        }
    }

    float4 a1v = *(const float4*)(asrc + lane * 4);
    float4 a2v = *(const float4*)(adst + lane * 4);
    #pragma unroll
    for (int r = 0; r < 8; r++) {
        int row = w * 8 + r;
        uint2 hv = *(const uint2*)&Hs[row][lane * 4];
        const __half* hp = reinterpret_cast<const __half*>(&hv);
        float f0 = __half2float(hp[0]), f1 = __half2float(hp[1]);
        float f2 = __half2float(hp[2]), f3 = __half2float(hp[3]);
        float d1 = f0 * a1v.x + f1 * a1v.y + f2 * a1v.z + f3 * a1v.w;
        float d2 = f0 * a2v.x + f1 * a2v.y + f2 * a2v.z + f3 * a2v.w;
        #pragma unroll
        for (int o = 16; o; o >>= 1) {
            d1 += __shfl_xor_sync(FULLM, d1, o);
            d2 += __shfl_xor_sync(FULLM, d2, o);
        }
        if (lane == 0 && m0 + row < M) {
            ssrc[m0 + row] = d1;
            sdst[m0 + row] = d2;
        }
    }
}

// ---------------- FUSED layer-1 agg + gemm2: k_agf ----------------
// Warp-per-node: verified online-softmax over h1 (fp16, d_out) -> o1 in regs;
// o1 staged per-warp in smem; h2 row = o1 @ W2 (W2 fp16 in smem, conflict-free);
// sdst2 via butterfly; h2 written fp16 to static (streamed).
// NOTE: sdst read (layer-1) and sdst2 write may alias: read-before-write per node.
__global__ void __launch_bounds__(256) k_agf(
        const __half* __restrict__ h,
        const float* __restrict__ asrc, const float* __restrict__ sdst,
        const float* __restrict__ bias, const float* __restrict__ W2,
        const float* __restrict__ a2d,
        __half* __restrict__ h2out, float* __restrict__ sdst2) {
    __shared__ __half2 sW2[HID][32];   // 16KB: sW2[k][j2] = W2[k][2j2..2j2+1]
    __shared__ float   sO[8][HID];     // 4KB per-warp o1 stage

    const int tid = threadIdx.x;
    const int w = tid >> 5;
    const int lane = tid & 31;

    // load W2 as fp16 (coalesced)
    for (int i = tid; i < HID * 32; i += 256) {
        int k = i >> 5, j2 = i & 31;
        sW2[k][j2] = __floats2half2_rn(W2[k * OUTD + 2 * j2], W2[k * OUTD + 2 * j2 + 1]);
    }
    __syncthreads();

    int node = (blockIdx.x * blockDim.x + tid) >> 5;
    if (node >= N_NODES) return;
    int beg = g_off[node], end = g_off[node + 1];
    float sd = sdst[node];
    float4 a1v = *(const float4*)(asrc + lane * 4);

    float m = -FLT_MAX, s = 0.f;
    float acc0 = 0.f, acc1 = 0.f, acc2 = 0.f, acc3 = 0.f;

    for (int c0 = beg; c0 < end; c0 += 32) {
        int n = min(32, end - c0);
        int cs = (lane < n) ? g_col[c0 + lane] : 0;

        int k = 0;
        for (; k + 4 <= n; k += 4) {
            int s0 = __shfl_sync(FULLM, cs, k);
            int s1 = __shfl_sync(FULLM, cs, k + 1);
            int s2 = __shfl_sync(FULLM, cs, k + 2);
            int s3 = __shfl_sync(FULLM, cs, k + 3);
            uint2 r0 = *(const uint2*)(h + (size_t)s0 * HID + lane * 4);
            uint2 r1 = *(const uint2*)(h + (size_t)s1 * HID + lane * 4);
            uint2 r2 = *(const uint2*)(h + (size_t)s2 * HID + lane * 4);
            uint2 r3 = *(const uint2*)(h + (size_t)s3 * HID + lane * 4);
            const __half* p0 = reinterpret_cast<const __half*>(&r0);
            const __half* p1 = reinterpret_cast<const __half*>(&r1);
            const __half* p2 = reinterpret_cast<const __half*>(&r2);
            const __half* p3 = reinterpret_cast<const __half*>(&r3);
            float f0a = __half2float(p0[0]), f0b = __half2float(p0[1]),
                  f0c = __half2float(p0[2]), f0d = __half2float(p0[3]);
            float f1a = __half2float(p1[0]), f1b = __half2float(p1[1]),
                  f1c = __half2float(p1[2]), f1d = __half2float(p1[3]);
            float f2a = __half2float(p2[0]), f2b = __half2float(p2[1]),
                  f2c = __half2float(p2[2]), f2d = __half2float(p2[3]);
            float f3a = __half2float(p3[0]), f3b = __half2float(p3[1]),
                  f3c = __half2float(p3[2]), f3d = __half2float(p3[3]);
            float d0 = f0a * a1v.x + f0b * a1v.y + f0c * a1v.z + f0d * a1v.w;
            float d1 = f1a * a1v.x + f1b * a1v.y + f1c * a1v.z + f1d * a1v.w;
            float d2 = f2a * a1v.x + f2b * a1v.y + f2c * a1v.z + f2d * a1v.w;
            float d3 = f3a * a1v.x + f3b * a1v.y + f3c * a1v.z + f3d * a1v.w;
            #pragma unroll
            for (int o = 16; o; o >>= 1) {
                d0 += __shfl_xor_sync(FULLM, d0, o);
                d1 += __shfl_xor_sync(FULLM, d1, o);
                d2 += __shfl_xor_sync(FULLM, d2, o);
                d3 += __shfl_xor_sync(FULLM, d3, o);
            }
            float e, mn, sc, wt;
            e = d0 + sd; e = (e > 0.f) ? e : NEG_SLOPE * e;
            mn = fmaxf(m, e); sc = __expf(m - mn); wt = __expf(e - mn);
            s = s * sc + wt;
            acc0 = acc0 * sc + wt * f0a; acc1 = acc1 * sc + wt * f0b;
            acc2 = acc2 * sc + wt * f0c; acc3 = acc3 * sc + wt * f0d;
            m = mn;
            e = d1 + sd; e = (e > 0.f) ? e : NEG_SLOPE * e;
            mn = fmaxf(m, e); sc = __expf(m - mn); wt = __expf(e - mn);
            s = s * sc + wt;
            acc0 = acc0 * sc + wt * f1a; acc1 = acc1 * sc + wt * f1b;
            acc2 = acc2 * sc + wt * f1c; acc3 = acc3 * sc + wt * f1d;
            m = mn;
            e = d2 + sd; e = (e > 0.f) ? e : NEG_SLOPE * e;
            mn = fmaxf(m, e); sc = __expf(m - mn); wt = __expf(e - mn);
            s = s * sc + wt;
            acc0 = acc0 * sc + wt * f2a; acc1 = acc1 * sc + wt * f2b;
            acc2 = acc2 * sc + wt * f2c; acc3 = acc3 * sc + wt * f2d;
            m = mn;
            e = d3 + sd; e = (e > 0.f) ? e : NEG_SLOPE * e;
            mn = fmaxf(m, e); sc = __expf(m - mn); wt = __expf(e - mn);
            s = s * sc + wt;
            acc0 = acc0 * sc + wt * f3a; acc1 = acc1 * sc + wt * f3b;
            acc2 = acc2 * sc + wt * f3c; acc3 = acc3 * sc + wt * f3d;
            m = mn;
        }
        for (; k < n; k++) {
            int s0 = __shfl_sync(FULLM, cs, k);
            uint2 r0 = *(const uint2*)(h + (size_t)s0 * HID + lane * 4);
            const __half* p0 = reinterpret_cast<const __half*>(&r0);
            float f0a = __half2float(p0[0]), f0b = __half2float(p0[1]),
                  f0c = __half2float(p0[2]), f0d = __half2float(p0[3]);
            float d0 = f0a * a1v.x + f0b * a1v.y + f0c * a1v.z + f0d * a1v.w;
            #pragma unroll
            for (int o = 16; o; o >>= 1) d0 += __shfl_xor_sync(FULLM, d0, o);
            float e = d0 + sd; e = (e > 0.f) ? e : NEG_SLOPE * e;
            float mn = fmaxf(m, e);
            float sc = __expf(m - mn);
            float wt = __expf(e - mn);
            s = s * sc + wt;
            acc0 = acc0 * sc + wt * f0a; acc1 = acc1 * sc + wt * f0b;
            acc2 = acc2 * sc + wt * f0c; acc3 = acc3 * sc + wt * f0d;
            m = mn;
        }
    }

    // o1 = elu(acc/s + bias)
    float inv = 1.f / s;
    float4 bv = *(const float4*)(bias + lane * 4);
    float r0 = acc0 * inv + bv.x;
    float r1 = acc1 * inv + bv.y;
    float r2 = acc2 * inv + bv.z;
    float r3 = acc3 * inv + bv.w;
    r0 = (r0 > 0.f) ? r0 : expm1f(r0);
    r1 = (r1 > 0.f) ? r1 : expm1f(r1);
    r2 = (r2 > 0.f) ? r2 : expm1f(r2);
    r3 = (r3 > 0.f) ? r3 : expm1f(r3);

    // ---- gemm2 in-warp: h2[j] = sum_k o1[k] * W2[k][j] ----
    sO[w][lane * 4 + 0] = r0;
    sO[w][lane * 4 + 1] = r1;
    sO[w][lane * 4 + 2] = r2;
    sO[w][lane * 4 + 3] = r3;
    __syncwarp();

    float h0 = 0.f, h1 = 0.f;
    #pragma unroll 8
    for (int k4 = 0; k4 < HID / 4; k4++) {
        float4 ov = *(const float4*)&sO[w][k4 * 4];
        float2 w0 = __half22float2(sW2[k4 * 4 + 0][lane]);
        float2 w1 = __half22float2(sW2[k4 * 4 + 1][lane]);
        float2 w2 = __half22float2(sW2[k4 * 4 + 2][lane]);
        float2 w3 = __half22float2(sW2[k4 * 4 + 3][lane]);
        h0 = fmaf(ov.x, w0.x, h0); h1 = fmaf(ov.x, w0.y, h1);
        h0 = fmaf(ov.y, w1.x, h0); h1 = fmaf(ov.y, w1.y, h1);
        h0 = fmaf(ov.z, w2.x, h0); h1 = fmaf(ov.z, w2.y, h1);
        h0 = fmaf(ov.w, w3.x, h0); h1 = fmaf(ov.w, w3.y, h1);
    }

    // sdst2 = h2 . a2d
    float2 a2 = *(const float2*)(a2d + lane * 2);
    float p = h0 * a2.x + h1 * a2.y;
    #pragma unroll
    for (int o = 16; o; o >>= 1) p += __shfl_xor_sync(FULLM, p, o);
    if (lane == 0) sdst2[node] = p;

    // h2 fp16 out (streamed)
    __half2 hh = __floats2half2_rn(h0, h1);
    *(unsigned*)(h2out + (size_t)node * OUTD + lane * 2) = *(unsigned*)&hh;
}

// ---------------- copy h2 fp16: static -> d_out upper half ----------------
__global__ void k_copyh(const __half* __restrict__ src, __half* __restrict__ dst) {
    int i = blockIdx.x * blockDim.x + threadIdx.x;   // uint4 = 8 halves
    if (i < N_NODES * (OUTD / 8)) ((uint4*)dst)[i] = ((const uint4*)src)[i];
}

// ---------------- layer-2 agg: fp16 h2 gathers, split output ----------------
__global__ void k_agg64(const __half* __restrict__ h,
                        const float* __restrict__ asrc, const float* __restrict__ sdst,
                        const float* __restrict__ bias,
                        float* __restrict__ outA,   // d_out lower half (nodes < N_HALF)
                        float* __restrict__ outB) { // static stage (nodes >= N_HALF)
    int node = (blockIdx.x * blockDim.x + threadIdx.x) >> 5;
    if (node >= N_NODES) return;
    int lane = threadIdx.x & 31;
    int beg = g_off[node], end = g_off[node + 1];
    float sd = sdst[node];
    float2 a1v = *(const float2*)(asrc + lane * 2);

    float m = -FLT_MAX, s = 0.f;
    float acc0 = 0.f, acc1 = 0.f;

    for (int c0 = beg; c0 < end; c0 += 32) {
        int n = min(32, end - c0);
        int cs = (lane < n) ? g_col[c0 + lane] : 0;

        int k = 0;
        for (; k + 4 <= n; k += 4) {
            int s0 = __shfl_sync(FULLM, cs, k);
            int s1 = __shfl_sync(FULLM, cs, k + 1);
            int s2 = __shfl_sync(FULLM, cs, k + 2);
            int s3 = __shfl_sync(FULLM, cs, k + 3);
            unsigned u0 = *(const unsigned*)(h + (size_t)s0 * OUTD + lane * 2);
            unsigned u1 = *(const unsigned*)(h + (size_t)s1 * OUTD + lane * 2);
            unsigned u2 = *(const unsigned*)(h + (size_t)s2 * OUTD + lane * 2);
            unsigned u3 = *(const unsigned*)(h + (size_t)s3 * OUTD + lane * 2);
            float2 v0 = __half22float2(*(__half2*)&u0);
            float2 v1 = __half22float2(*(__half2*)&u1);
            float2 v2 = __half22float2(*(__half2*)&u2);
            float2 v3 = __half22float2(*(__half2*)&u3);
            float d0 = v0.x * a1v.x + v0.y * a1v.y;
            float d1 = v1.x * a1v.x + v1.y * a1v.y;
            float d2 = v2.x * a1v.x + v2.y * a1v.y;
            float d3 = v3.x * a1v.x + v3.y * a1v.y;
            #pragma unroll
            for (int o = 16; o; o >>= 1) {
                d0 += __shfl_xor_sync(FULLM, d0, o);
                d1 += __shfl_xor_sync(FULLM, d1, o);
                d2 += __shfl_xor_sync(FULLM, d2, o);
                d3 += __shfl_xor_sync(FULLM, d3, o);
            }
            float e, mn, sc, wt;
            e = d0 + sd; e = (e > 0.f) ? e : NEG_SLOPE * e;
            mn = fmaxf(m, e); sc = __expf(m - mn); wt = __expf(e - mn);
            s = s * sc + wt;
            acc0 = acc0 * sc + wt * v0.x; acc1 = acc1 * sc + wt * v0.y;
            m = mn;
            e = d1 + sd; e = (e > 0.f) ? e : NEG_SLOPE * e;
            mn = fmaxf(m, e); sc = __expf(m - mn); wt = __expf(e - mn);
            s = s * sc + wt;
            acc0 = acc0 * sc + wt * v1.x; acc1 = acc1 * sc + wt * v1.y;
            m = mn;
            e = d2 + sd; e = (e > 0.f) ? e : NEG_SLOPE * e;
            mn = fmaxf(m, e); sc = __expf(m - mn); wt = __expf(e - mn);
            s = s * sc + wt;
            acc0 = acc0 * sc + wt * v2.x; acc1 = acc1 * sc + wt * v2.y;
            m = mn;
            e = d3 + sd; e = (e > 0.f) ? e : NEG_SLOPE * e;
            mn = fmaxf(m, e); sc = __expf(m - mn); wt = __expf(e - mn);
            s = s * sc + wt;
            acc0 = acc0 * sc + wt * v3.x; acc1 = acc1 * sc + wt * v3.y;
            m = mn;
        }
        for (; k < n; k++) {
            int s0 = __shfl_sync(FULLM, cs, k);
            unsigned u0 = *(const unsigned*)(h + (size_t)s0 * OUTD + lane * 2);
            float2 v0 = __half22float2(*(__half2*)&u0);
            float d0 = v0.x * a1v.x + v0.y * a1v.y;
            #pragma unroll
            for (int o = 16; o; o >>= 1) d0 += __shfl_xor_sync(FULLM, d0, o);
            float e = d0 + sd; e = (e > 0.f) ? e : NEG_SLOPE * e;
            float mn = fmaxf(m, e);
            float sc = __expf(m - mn);
            float wt = __expf(e - mn);
            s = s * sc + wt;
            acc0 = acc0 * sc + wt * v0.x; acc1 = acc1 * sc + wt * v0.y;
            m = mn;
        }
    }

    float inv = 1.f / s;
    float2 bv = *(const float2*)(bias + lane * 2);
    float2 o2 = make_float2(acc0 * inv + bv.x, acc1 * inv + bv.y);
    float* op = (node < N_HALF)
        ? (outA + (size_t)node * OUTD)
        : (outB + (size_t)(node - N_HALF) * OUTD);
    *(float2*)(op + lane * 2) = o2;
}

// ---------------- copy second-half output: static -> d_out upper ----------------
__global__ void k_copy2(const float* __restrict__ src, float* __restrict__ dst) {
    int i = blockIdx.x * blockDim.x + threadIdx.x;   // float4
    if (i < N_HALF * (OUTD / 4)) ((float4*)dst)[i] = ((const float4*)src)[i];
}

// ---------------- launch ----------------
extern "C" void kernel_launch(void* const* d_in, const int* in_sizes, int n_in,
                              void* d_out, int out_size) {
    const float* x   = (const float*)d_in[0];
    const int*   ei  = (const int*)d_in[1];
    const float* W1  = (const float*)d_in[2];
    const float* a1s = (const float*)d_in[3];
    const float* a1d = (const float*)d_in[4];
    const float* b1  = (const float*)d_in[5];
    const float* W2  = (const float*)d_in[6];
    const float* a2s = (const float*)d_in[7];
    const float* a2d = (const float*)d_in[8];
    const float* b2  = (const float*)d_in[9];

    // d_out (25.6MB device), phased:
    //   phase 1: h1 fp16 [N,128] (full 25.6MB) — gemm1 writes, k_agf gathers
    //   phase 2: h2 fp16 [N,64] in UPPER half [12.8,25.6MB) — k_copyh writes,
    //            k_agg64 gathers; output fp32 nodes<N/2 go to LOWER half (disjoint)
    //   phase 3: k_copy2 lands nodes>=N/2 output in upper half (h2 dead)
    __half* h1h   = (__half*)d_out;
    __half* h2dst = (__half*)d_out + (size_t)N_NODES * OUTD;   // upper half
    float*  outF  = (float*)d_out;

    const int nodeBlk = (N_NODES + 255) / 256;
    const int edgeBlk = (ETOT + 255) / 256;
    const int warpBlk = (N_NODES * 32 + 255) / 256;
    const int gBlk    = (N_NODES + 63) / 64;
    const int chBlk   = (N_NODES * (OUTD / 8) + 255) / 256;
    const int c2Blk   = (N_HALF * (OUTD / 4) + 255) / 256;

    k_zeroA<<<nodeBlk, 256>>>();                                             // 0
    k_count<<<edgeBlk, 256>>>(ei);                                           // 1
    k_zeroB<<<nodeBlk, 256>>>();                                             // 2
    k_gemm1_mma<<<gBlk, 256>>>(x, W1, h1h, a1s, a1d,
                               g_ssrc, g_sdst, N_NODES);                     // 3 <- ncu
    k_scan1<<<SCAN_NB, 256>>>();                                             // 4
    k_scan2<<<1, 512>>>(SCAN_NB);                                            // 5
    k_scan3<<<SCAN_NB, 256>>>();                                             // 6
    k_fill<<<edgeBlk, 256>>>(ei);                                            // 7
    k_agf<<<warpBlk, 256>>>(h1h, a1s, g_sdst, b1, W2, a2d,
                            g_h2h, g_sdst);                                  // 8
    k_copyh<<<chBlk, 256>>>(g_h2h, h2dst);                                   // 9
    k_agg64<<<warpBlk, 256>>>(h2dst, a2s, g_sdst, b2, outF, g_o2b);          // 10
    k_copy2<<<c2Blk, 256>>>(g_o2b, outF + (size_t)N_HALF * OUTD);            // 11
}